// round 13
// baseline (speedup 1.0000x reference)
#include <cuda_runtime.h>
#include <cuda_bf16.h>

#define NNODES 8192
#define NEDGES 262144
#define NFEAT  128
#define NREP   4
#define CAP    48        // max edges per (row, rep) sub-bucket

// ---------------- device scratch (no allocation allowed) ----------------
__device__ __align__(16) float g_support[NNODES * NFEAT];        // x @ W (4 MB)
__device__ __align__(16) float g_dinv[NNODES];
// cnt4 and deg4 adjacent -> one memset clears both
struct ZeroBlk { int cnt4[NNODES * NREP]; float deg4[NNODES * NREP]; };
__device__ __align__(16) ZeroBlk g_z;
__device__ __align__(16) int2  g_bucket[NNODES * NREP * CAP];    // {col, w} (12.6 MB)

// ---------------- K1: single-pass bucketed scatter + degree ----------------
__global__ void k_scatter(const int* __restrict__ rows,
                          const int* __restrict__ cols,
                          const float* __restrict__ ew) {
    int e = blockIdx.x * blockDim.x + threadIdx.x;
    int r = rows[e];
    float w = ew[e];
    int slot = r * 4 + (e & 3);
    int pos = atomicAdd(&g_z.cnt4[slot], 1);
    g_bucket[slot * CAP + pos] = make_int2(cols[e], __float_as_int(w));
    atomicAdd(&g_z.deg4[slot], w);
}

// ---------------- K2: dinv = rsqrt(1 + deg + eps)  (elementwise) ------------
__global__ void k_dinv() {
    int i = blockIdx.x * blockDim.x + threadIdx.x;
    if (i < NNODES) {
        float4 d = *(const float4*)&g_z.deg4[i * 4];
        g_dinv[i] = rsqrtf(1.0f + d.x + d.y + d.z + d.w + 1e-10f);
    }
}

// ---------------- packed f32x2 helpers ----------------
__device__ __forceinline__ unsigned long long pack2(float lo, float hi) {
    unsigned long long r;
    asm("mov.b64 %0, {%1, %2};" : "=l"(r) : "f"(lo), "f"(hi));
    return r;
}
__device__ __forceinline__ void fma2(unsigned long long& d,
                                     unsigned long long a,
                                     unsigned long long b) {
    asm("fma.rn.f32x2 %0, %1, %2, %0;" : "+l"(d) : "l"(a), "l"(b));
}
__device__ __forceinline__ float2 unpack2(unsigned long long p) {
    float lo, hi;
    asm("mov.b64 {%0, %1}, %2;" : "=f"(lo), "=f"(hi) : "l"(p));
    return make_float2(lo, hi);
}

// ---------------- K3: support = x @ W  (8192x128x128 fp32, f32x2 FMA) -------
__global__ __launch_bounds__(256) void k_gemm(const float* __restrict__ x,
                                              const float* __restrict__ w) {
    __shared__ __align__(16) float s_x[32][32];
    __shared__ __align__(16) float s_w[32][128];
    int tid = threadIdx.x;
    int row_base = blockIdx.x * 32;
    int c0 = (tid & 31) * 4;
    int r0 = (tid >> 5) * 4;

    unsigned long long acc2[4][2];
#pragma unroll
    for (int i = 0; i < 4; i++) { acc2[i][0] = 0ull; acc2[i][1] = 0ull; }

    for (int kk = 0; kk < 128; kk += 32) {
#pragma unroll
        for (int q = 0; q < 4; q++) {
            int e = tid + 256 * q;
            int r = e >> 5, kl = e & 31;
            s_x[r][kl] = x[(row_base + r) * 128 + kk + kl];
        }
#pragma unroll
        for (int q = 0; q < 4; q++) {
            int p = tid + 256 * q;
            int kr = p >> 5, cc = (p & 31) * 4;
            *(float4*)&s_w[kr][cc] = *(const float4*)&w[(kk + kr) * 128 + cc];
        }
        __syncthreads();
#pragma unroll
        for (int k = 0; k < 32; k++) {
            float4 bv = *(float4*)&s_w[k][c0];
            unsigned long long b01 = pack2(bv.x, bv.y);
            unsigned long long b23 = pack2(bv.z, bv.w);
#pragma unroll
            for (int i = 0; i < 4; i++) {
                float av = s_x[r0 + i][k];
                unsigned long long aa = pack2(av, av);
                fma2(acc2[i][0], aa, b01);
                fma2(acc2[i][1], aa, b23);
            }
        }
        __syncthreads();
    }
#pragma unroll
    for (int i = 0; i < 4; i++) {
        float2 lo = unpack2(acc2[i][0]);
        float2 hi = unpack2(acc2[i][1]);
        *(float4*)&g_support[(row_base + r0 + i) * 128 + c0] =
            make_float4(lo.x, lo.y, hi.x, hi.y);
    }
}

// ---------------- K4: SpMM, cross-rep interleaved, L1-bypassing gathers -----
__device__ __forceinline__ void acc_edge(const int2* __restrict__ bk, int i,
                                         int foff,
                                         float& ax, float& ay,
                                         float& az, float& aw) {
    int2 e = __ldcs(&bk[i]);                       // streaming: read-once
    float v = __int_as_float(e.y) * g_dinv[e.x];
    float4 s = __ldcg((const float4*)&g_support[e.x * 128 + foff]);  // L2-only
    ax += v * s.x; ay += v * s.y; az += v * s.z; aw += v * s.w;
}

__global__ __launch_bounds__(256) void k_spmm(const float* __restrict__ bias,
                                              float* __restrict__ out) {
    int warp = (blockIdx.x * blockDim.x + threadIdx.x) >> 5;
    int lane = threadIdx.x & 31;
    if (warp >= NNODES) return;
    int row = warp;
    float di = g_dinv[row];
    int4 cnt = *(const int4*)&g_z.cnt4[row * 4];
    int n0 = cnt.x, n1 = cnt.y, n2 = cnt.z, n3 = cnt.w;
    int nmax = max(max(n0, n1), max(n2, n3));

    const int2* b0 = &g_bucket[(row * 4 + 0) * CAP];
    const int2* b1 = &g_bucket[(row * 4 + 1) * CAP];
    const int2* b2 = &g_bucket[(row * 4 + 2) * CAP];
    const int2* b3 = &g_bucket[(row * 4 + 3) * CAP];

    float ax = 0.f, ay = 0.f, az = 0.f, aw = 0.f;
    int foff = lane * 4;

    for (int i = 0; i < nmax; i++) {
        if (i < n0) acc_edge(b0, i, foff, ax, ay, az, aw);
        if (i < n1) acc_edge(b1, i, foff, ax, ay, az, aw);
        if (i < n2) acc_edge(b2, i, foff, ax, ay, az, aw);
        if (i < n3) acc_edge(b3, i, foff, ax, ay, az, aw);
    }
    // self-loop: dinv[row]^2 * support[row]
    {
        float4 sv = __ldcg((const float4*)&g_support[row * 128 + foff]);
        ax += di * sv.x; ay += di * sv.y; az += di * sv.z; aw += di * sv.w;
    }
    float4 b = *(const float4*)&bias[foff];
    float4 o;
    o.x = di * ax + b.x;
    o.y = di * ay + b.y;
    o.z = di * az + b.z;
    o.w = di * aw + b.w;
    *(float4*)&out[row * 128 + foff] = o;
}

// ---------------- launch ----------------
extern "C" void kernel_launch(void* const* d_in, const int* in_sizes, int n_in,
                              void* d_out, int out_size) {
    const float* x    = (const float*)d_in[0];
    const int*   adj  = (const int*)d_in[1];     // int32 [2, E]
    const float* ew   = (const float*)d_in[2];
    const float* wgt  = (const float*)d_in[3];
    const float* bias = (const float*)d_in[4];
    float* out = (float*)d_out;

    const int* rows = adj;
    const int* cols = adj + NEDGES;

    // one-time side resources (host-side only; no device allocation)
    static cudaStream_t s2 = nullptr;
    static cudaEvent_t evA = nullptr, evB = nullptr;
    if (s2 == nullptr) {
        cudaStreamCreateWithFlags(&s2, cudaStreamNonBlocking);
        cudaEventCreateWithFlags(&evA, cudaEventDisableTiming);
        cudaEventCreateWithFlags(&evB, cudaEventDisableTiming);
    }

    // fork: GEMM (depends only on x, W) runs concurrently with the bucket build
    cudaEventRecord(evA, 0);
    cudaStreamWaitEvent(s2, evA, 0);
    k_gemm<<<NNODES / 32, 256, 0, s2>>>(x, wgt);
    cudaEventRecord(evB, s2);

    // bucket build on the main (capture) stream (one memset clears cnt+deg)
    void* z_ptr = nullptr; cudaGetSymbolAddress(&z_ptr, g_z);
    cudaMemsetAsync(z_ptr, 0, sizeof(ZeroBlk), 0);
    k_scatter<<<NEDGES / 256, 256>>>(rows, cols, ew);
    k_dinv<<<NNODES / 256, 256>>>();

    // join, then SpMM (warp per row)
    cudaStreamWaitEvent(0, evB, 0);
    k_spmm<<<NNODES / 8, 256>>>(bias, out);
}